// round 7
// baseline (speedup 1.0000x reference)
#include <cuda_runtime.h>
#include <cuda_fp16.h>
#include <math.h>
#include <stdint.h>

#define TT   8192
#define DD   2048
#define NE   8
#define BB   512
#define NBK  16

#define BM   128
#define BN   128
#define BK   64
#define LDA  72                      // halves per smem row (128B data + 16B pad)
#define STAGE_B (256 * LDA * 2)      // 36864 B (128 A rows + 128 B rows)
#define DSMEM   (2 * STAGE_B)        // 73728 B

// ---------------- scratch (static device globals) ----------------
__device__ int    g_cnt[NBK];
__device__ int    g_tok[NBK][TT];
__device__ float  g_twt[NBK][TT];
__device__ int    g_sel[TT][2];
__device__ float  g_wgt[TT][2];
__device__ __align__(16) __half xs[TT][DD];
__device__ __align__(16) __half wdp[NE][BB][DD];
__device__ __align__(16) __half wup[NE][DD][BB];
__device__ __align__(16) __half wsdp[BB][DD];
__device__ __align__(16) __half wsup[DD][BB];
__device__ __align__(16) __half ghp[2][TT][BB];
__device__ __align__(16) __half ghsp[TT][BB];

__device__ __forceinline__ uint32_t smem_u32(const void* p) {
    uint32_t a;
    asm("{ .reg .u64 t; cvta.to.shared.u64 t, %1; cvt.u32.u64 %0, t; }" : "=r"(a) : "l"(p));
    return a;
}
__device__ __forceinline__ void ldsm4(uint32_t* r, uint32_t a) {
    asm volatile("ldmatrix.sync.aligned.m8n8.x4.shared.b16 {%0,%1,%2,%3}, [%4];"
                 : "=r"(r[0]), "=r"(r[1]), "=r"(r[2]), "=r"(r[3]) : "r"(a));
}
__device__ __forceinline__ void mma16816(float* c, const uint32_t* a, const uint32_t* b) {
    asm volatile("mma.sync.aligned.m16n8k16.row.col.f32.f16.f16.f32 "
                 "{%0,%1,%2,%3}, {%4,%5,%6,%7}, {%8,%9}, {%0,%1,%2,%3};"
                 : "+f"(c[0]), "+f"(c[1]), "+f"(c[2]), "+f"(c[3])
                 : "r"(a[0]), "r"(a[1]), "r"(a[2]), "r"(a[3]), "r"(b[0]), "r"(b[1]));
}
#define CPA16(dst, src, sz) \
    asm volatile("cp.async.cg.shared.global [%0], [%1], 16, %2;" \
                 :: "r"(dst), "l"(src), "r"(sz) : "memory")
#define CPC()  asm volatile("cp.async.commit_group;" ::: "memory")
#define CPW(n) asm volatile("cp.async.wait_group %0;" :: "n"(n) : "memory")

__device__ __forceinline__ uint32_t packh(half a, half b) {
    __half2 h = __halves2half2(a, b);
    return *(uint32_t*)&h;
}
__device__ __forceinline__ float gelu_f(float v) {
    return 0.5f * v * (1.0f + erff(v * 0.70710678118654752f));
}

// ---------------- setup kernels ----------------
__global__ void k_reset() {
    if (threadIdx.x < NBK) g_cnt[threadIdx.x] = 0;
}

// fp32 -> fp16 (plain), 8 elems/thread
__global__ void k_cvt(const float* __restrict__ s, __half* __restrict__ d, int n) {
    int stride = gridDim.x * blockDim.x;
    for (int i = blockIdx.x * blockDim.x + threadIdx.x; i < n / 8; i += stride) {
        float4 v0 = ((const float4*)s)[2 * i];
        float4 v1 = ((const float4*)s)[2 * i + 1];
        uint4 o;
        o.x = packh(__float2half_rn(v0.x), __float2half_rn(v0.y));
        o.y = packh(__float2half_rn(v0.z), __float2half_rn(v0.w));
        o.z = packh(__float2half_rn(v1.x), __float2half_rn(v1.y));
        o.w = packh(__float2half_rn(v1.z), __float2half_rn(v1.w));
        *(uint4*)(d + i * 8) = o;
    }
}

// routing (fp32 logits) + x fp16 conversion; one warp per token
__global__ void k_route(const float* __restrict__ x, const float* __restrict__ gw) {
    int t    = blockIdx.x * 8 + (threadIdx.x >> 5);
    int lane = threadIdx.x & 31;
    if (t >= TT) return;
    const float4* xr = (const float4*)(x + (size_t)t * DD);
    float acc[NE];
#pragma unroll
    for (int e = 0; e < NE; e++) acc[e] = 0.f;
    for (int i = lane; i < DD / 4; i += 32) {
        float4 xv = xr[i];
        *(uint2*)(&xs[t][i * 4]) = make_uint2(
            packh(__float2half_rn(xv.x), __float2half_rn(xv.y)),
            packh(__float2half_rn(xv.z), __float2half_rn(xv.w)));
#pragma unroll
        for (int e = 0; e < NE; e++) {
            float4 gv = ((const float4*)(gw + (size_t)e * DD))[i];
            acc[e] += xv.x * gv.x + xv.y * gv.y + xv.z * gv.z + xv.w * gv.w;
        }
    }
#pragma unroll
    for (int e = 0; e < NE; e++)
#pragma unroll
        for (int o = 16; o > 0; o >>= 1)
            acc[e] += __shfl_down_sync(0xffffffffu, acc[e], o);
    if (lane == 0) {
        float mx = acc[0];
#pragma unroll
        for (int e = 1; e < NE; e++) mx = fmaxf(mx, acc[e]);
        float p[NE];
#pragma unroll
        for (int e = 0; e < NE; e++) p[e] = expf(acc[e] - mx);
        int i1 = 0;
#pragma unroll
        for (int e = 1; e < NE; e++) if (p[e] > p[i1]) i1 = e;
        int i2 = (i1 == 0) ? 1 : 0;
#pragma unroll
        for (int e = 0; e < NE; e++) { if (e != i1 && p[e] > p[i2]) i2 = e; }
        float w1 = p[i1], w2 = p[i2];
        float inv = 1.0f / (w1 + w2);
        w1 *= inv; w2 *= inv;
        g_sel[t][0] = i1; g_sel[t][1] = i2;
        g_wgt[t][0] = w1; g_wgt[t][1] = w2;
        int b0 = i1 * 2;
        int s0 = atomicAdd(&g_cnt[b0], 1);
        g_tok[b0][s0] = t; g_twt[b0][s0] = w1;
        int b1 = i2 * 2 + 1;
        int s1 = atomicAdd(&g_cnt[b1], 1);
        g_tok[b1][s1] = t; g_twt[b1][s1] = w2;
    }
}

// ---------------- single-pass fp16 mma GEMM, cp.async double-buffered ----------------
enum { DOWN_S = 0, DOWN_R = 1, UP_S = 2, UP_R = 3 };

template <int MODE>
__global__ __launch_bounds__(256, 2) void k_mma(
    const float* __restrict__ bias, const float* __restrict__ bu,
    float* __restrict__ out, int kk)
{
    extern __shared__ char dyn[];
    __shared__ int   s_row[BM];
    __shared__ float s_wt[BM];

    const int tid = threadIdx.x, wid = tid >> 5, lane = tid & 31;
    const int m0 = blockIdx.x * BM, n0 = blockIdx.y * BN;

    int M = TT, eidx = 0, kidx = 0;
    const int* tok = nullptr;
    const float* twt = nullptr;
    if (MODE == DOWN_R || MODE == UP_R) {
        int bucket = (MODE == DOWN_R) ? (int)blockIdx.z : ((int)blockIdx.z * 2 + kk);
        M = g_cnt[bucket];
        if (m0 >= M) return;
        eidx = bucket >> 1;
        kidx = bucket & 1;
        tok = g_tok[bucket];
        twt = g_twt[bucket];
    }

    const __half* Ah; int lda;
    const __half* Bh; int ldb; int Kd;
    if (MODE == DOWN_S)      { Ah = &xs[0][0];        lda = DD; Bh = &wsdp[0][0];       ldb = DD; Kd = DD; }
    else if (MODE == DOWN_R) { Ah = &xs[0][0];        lda = DD; Bh = &wdp[eidx][0][0];  ldb = DD; Kd = DD; }
    else if (MODE == UP_S)   { Ah = &ghsp[0][0];      lda = BB; Bh = &wsup[0][0];       ldb = BB; Kd = BB; }
    else                     { Ah = &ghp[kk][0][0];   lda = BB; Bh = &wup[eidx][0][0];  ldb = BB; Kd = BB; }

    if (tid < BM) {
        int r = m0 + tid;
        if (MODE == DOWN_R || MODE == UP_R) {
            s_row[tid] = (r < M) ? tok[r] : -1;
            s_wt[tid]  = (r < M) ? twt[r] : 0.f;
        } else {
            s_row[tid] = r;
        }
    }
    __syncthreads();

    // cp.async: thread -> rows {lrow + 32*j}, 16B chunk lch (BK=64 -> 128B/row)
    const int lrow = tid >> 3, lch = tid & 7;
    const char* pA[4];
    uint32_t amask = 0;
#pragma unroll
    for (int j = 0; j < 4; j++) {
        int r = lrow + 32 * j;               // A row 0..127
        int sr = s_row[r];
        uint32_t ok = 1;
        if (MODE == DOWN_R || MODE == UP_R) {
            if (sr < 0) { sr = 0; ok = 0; }
        }
        amask |= ok << j;
        pA[j] = (const char*)(Ah + (size_t)sr * lda) + lch * 16;
    }
    const char* pB = (const char*)(Bh + (size_t)(n0 + lrow) * ldb) + lch * 16;
    const size_t bstride = (size_t)32 * ldb * 2;

    const uint32_t sb0 = smem_u32(dyn);
    const uint32_t sp0 = sb0 + (lrow * LDA + lch * 8) * 2;
    const uint32_t rowstep = 32 * LDA * 2;

    auto issue = [&](int stage) {
        uint32_t st = stage ? (uint32_t)STAGE_B : 0u;
#pragma unroll
        for (int j = 0; j < 4; j++)
            CPA16(sp0 + st + j * rowstep, pA[j], ((amask >> j) & 1) * 16);
#pragma unroll
        for (int j = 0; j < 4; j++)
            CPA16(sp0 + st + (j + 4) * rowstep, pB + j * bstride, 16);
        CPC();
#pragma unroll
        for (int j = 0; j < 4; j++) pA[j] += 128;
        pB += 128;
    };

    const int warp_m = wid >> 2, warp_n = wid & 3;   // 2 x 4 warps, 64x32 each
    float c[4][4][4];
#pragma unroll
    for (int i = 0; i < 4; i++)
#pragma unroll
        for (int j = 0; j < 4; j++)
#pragma unroll
            for (int q = 0; q < 4; q++) c[i][j][q] = 0.f;

    const int nch = Kd / BK;
    issue(0);

    for (int ch = 0; ch < nch; ch++) {
        if (ch + 1 < nch) { issue((ch + 1) & 1); CPW(1); }
        else              { CPW(0); }
        __syncthreads();

        const uint32_t sbase = sb0 + (ch & 1) * STAGE_B;
#pragma unroll
        for (int ks = 0; ks < 4; ks++) {
            uint32_t a[4][4], b[4][2];
            int arow = warp_m * 64 + (lane & 15);
            int acol = ks * 16 + (lane >> 4) * 8;
#pragma unroll
            for (int mt = 0; mt < 4; mt++)
                ldsm4(a[mt], sbase + ((arow + mt * 16) * LDA + acol) * 2);
            // B: rows 128+, ldsm4 loads two n-groups per issue
#pragma unroll
            for (int p = 0; p < 2; p++) {
                int brow = 128 + warp_n * 32 + p * 16 + ((lane >> 4) & 1) * 8 + (lane & 7);
                int bcol = ks * 16 + ((lane >> 3) & 1) * 8;
                uint32_t r4[4];
                ldsm4(r4, sbase + (brow * LDA + bcol) * 2);
                b[2 * p][0] = r4[0]; b[2 * p][1] = r4[1];
                b[2 * p + 1][0] = r4[2]; b[2 * p + 1][1] = r4[3];
            }
#pragma unroll
            for (int mt = 0; mt < 4; mt++)
#pragma unroll
                for (int nt = 0; nt < 4; nt++) mma16816(c[mt][nt], a[mt], b[nt]);
        }
        __syncthreads();
    }

    // ---------------- epilogue ----------------
    const int cbase = n0 + warp_n * 32 + (lane & 3) * 2;
#pragma unroll
    for (int mt = 0; mt < 4; mt++) {
#pragma unroll
        for (int half_i = 0; half_i < 2; half_i++) {
            int r = warp_m * 64 + mt * 16 + (lane >> 2) + half_i * 8;
            int t = s_row[r];
            if (t < 0) continue;
            float wgt = (MODE == DOWN_R) ? s_wt[r] : 0.f;
            int sel0 = 0, sel1 = 0; float w0 = 0.f, w1 = 0.f;
            if (MODE == UP_S) {
                sel0 = g_sel[t][0]; sel1 = g_sel[t][1];
                w0 = g_wgt[t][0];   w1 = g_wgt[t][1];
            }
#pragma unroll
            for (int nt = 0; nt < 4; nt++) {
                int n = cbase + nt * 8;
                float v0 = c[mt][nt][half_i * 2 + 0];
                float v1 = c[mt][nt][half_i * 2 + 1];
                if (MODE == DOWN_S) {
                    float o0 = gelu_f(v0 + bias[n]);
                    float o1 = gelu_f(v1 + bias[n + 1]);
                    *(uint32_t*)&ghsp[t][n] = packh(__float2half_rn(o0), __float2half_rn(o1));
                } else if (MODE == DOWN_R) {
                    const float* bp = bias + (size_t)eidx * BB + n;
                    float o0 = gelu_f(v0 + bp[0]) * wgt;
                    float o1 = gelu_f(v1 + bp[1]) * wgt;
                    *(uint32_t*)&ghp[kidx][t][n] = packh(__float2half_rn(o0), __float2half_rn(o1));
                } else if (MODE == UP_S) {
                    const float* b0p = bu + (size_t)sel0 * DD + n;
                    const float* b1p = bu + (size_t)sel1 * DD + n;
                    float2 o;
                    o.x = v0 + bias[n]     + w0 * b0p[0] + w1 * b1p[0];
                    o.y = v1 + bias[n + 1] + w0 * b0p[1] + w1 * b1p[1];
                    *(float2*)(out + (size_t)t * DD + n) = o;
                } else { // UP_R: race-free += (one slot per token per launch)
                    float* dp = out + (size_t)t * DD + n;
                    float2 old = *(float2*)dp;
                    old.x += v0; old.y += v1;
                    *(float2*)dp = old;
                }
            }
        }
    }
}

extern "C" void kernel_launch(void* const* d_in, const int* in_sizes, int n_in,
                              void* d_out, int out_size) {
    const float* x   = (const float*)d_in[0];
    const float* gw  = (const float*)d_in[1];
    const float* wd  = (const float*)d_in[2];
    const float* bd  = (const float*)d_in[3];
    const float* wu  = (const float*)d_in[4];
    const float* bu  = (const float*)d_in[5];
    const float* wsd = (const float*)d_in[6];
    const float* bsd = (const float*)d_in[7];
    const float* wsu = (const float*)d_in[8];
    const float* bsu = (const float*)d_in[9];
    float* out = (float*)d_out;

    cudaFuncSetAttribute(k_mma<DOWN_S>, cudaFuncAttributeMaxDynamicSharedMemorySize, DSMEM);
    cudaFuncSetAttribute(k_mma<DOWN_R>, cudaFuncAttributeMaxDynamicSharedMemorySize, DSMEM);
    cudaFuncSetAttribute(k_mma<UP_S>,   cudaFuncAttributeMaxDynamicSharedMemorySize, DSMEM);
    cudaFuncSetAttribute(k_mma<UP_R>,   cudaFuncAttributeMaxDynamicSharedMemorySize, DSMEM);

    __half *p_wd, *p_wu, *p_wsd, *p_wsu;
    cudaGetSymbolAddress((void**)&p_wd,  wdp);
    cudaGetSymbolAddress((void**)&p_wu,  wup);
    cudaGetSymbolAddress((void**)&p_wsd, wsdp);
    cudaGetSymbolAddress((void**)&p_wsu, wsup);

    k_reset<<<1, 32>>>();
    k_cvt<<<2048, 256>>>(wd,  p_wd,  NE * BB * DD);
    k_cvt<<<2048, 256>>>(wu,  p_wu,  NE * DD * BB);
    k_cvt<<<512, 256>>>(wsd, p_wsd, BB * DD);
    k_cvt<<<512, 256>>>(wsu, p_wsu, DD * BB);
    k_route<<<TT / 8, 256>>>(x, gw);

    k_mma<DOWN_S><<<dim3(TT / BM, BB / BN), 256, DSMEM>>>(bsd, nullptr, nullptr, 0);
    k_mma<DOWN_R><<<dim3(TT / BM, BB / BN, NBK), 256, DSMEM>>>(bd, nullptr, nullptr, 0);
    k_mma<UP_S><<<dim3(TT / BM, DD / BN), 256, DSMEM>>>(bsu, bu, out, 0);
    k_mma<UP_R><<<dim3(TT / BM, DD / BN, NE), 256, DSMEM>>>(nullptr, nullptr, out, 0);
    k_mma<UP_R><<<dim3(TT / BM, DD / BN, NE), 256, DSMEM>>>(nullptr, nullptr, out, 1);
}

// round 8
// speedup vs baseline: 1.0004x; 1.0004x over previous
#include <cuda_runtime.h>
#include <cuda_fp16.h>
#include <math.h>
#include <stdint.h>

#define TT   8192
#define DD   2048
#define NE   8
#define BB   512
#define NBK  16

#define BM   128
#define BN   128
#define BK   64
#define LDA  72                      // halves per smem row (128B data + 16B pad)
#define STAGE_B (256 * LDA * 2)      // 36864 B (128 A rows + 128 B rows)
#define DSMEM   (2 * STAGE_B)        // 73728 B

// ---------------- scratch (static device globals) ----------------
__device__ int    g_cnt[NBK];
__device__ int    g_tok[NBK][TT];
__device__ float  g_twt[NBK][TT];
__device__ int    g_sel[TT][2];
__device__ float  g_wgt[TT][2];
__device__ __align__(16) __half xs[TT][DD];
__device__ __align__(16) __half wdp[NE][BB][DD];
__device__ __align__(16) __half wup[NE][DD][BB];
__device__ __align__(16) __half wsdp[BB][DD];
__device__ __align__(16) __half wsup[DD][BB];
__device__ __align__(16) __half ghp[2][TT][BB];
__device__ __align__(16) __half ghsp[TT][BB];

__device__ __forceinline__ uint32_t smem_u32(const void* p) {
    uint32_t a;
    asm("{ .reg .u64 t; cvta.to.shared.u64 t, %1; cvt.u32.u64 %0, t; }" : "=r"(a) : "l"(p));
    return a;
}
__device__ __forceinline__ void ldsm4(uint32_t* r, uint32_t a) {
    asm volatile("ldmatrix.sync.aligned.m8n8.x4.shared.b16 {%0,%1,%2,%3}, [%4];"
                 : "=r"(r[0]), "=r"(r[1]), "=r"(r[2]), "=r"(r[3]) : "r"(a));
}
__device__ __forceinline__ void mma16816(float* c, const uint32_t* a, const uint32_t* b) {
    asm volatile("mma.sync.aligned.m16n8k16.row.col.f32.f16.f16.f32 "
                 "{%0,%1,%2,%3}, {%4,%5,%6,%7}, {%8,%9}, {%0,%1,%2,%3};"
                 : "+f"(c[0]), "+f"(c[1]), "+f"(c[2]), "+f"(c[3])
                 : "r"(a[0]), "r"(a[1]), "r"(a[2]), "r"(a[3]), "r"(b[0]), "r"(b[1]));
}
#define CPA16(dst, src, sz) \
    asm volatile("cp.async.cg.shared.global [%0], [%1], 16, %2;" \
                 :: "r"(dst), "l"(src), "r"(sz) : "memory")
#define CPC()  asm volatile("cp.async.commit_group;" ::: "memory")
#define CPW(n) asm volatile("cp.async.wait_group %0;" :: "n"(n) : "memory")

__device__ __forceinline__ uint32_t packh(half a, half b) {
    __half2 h = __halves2half2(a, b);
    return *(uint32_t*)&h;
}
__device__ __forceinline__ float gelu_f(float v) {
    return 0.5f * v * (1.0f + erff(v * 0.70710678118654752f));
}

// ---------------- setup kernels ----------------
__global__ void k_reset() {
    if (threadIdx.x < NBK) g_cnt[threadIdx.x] = 0;
}

// fp32 -> fp16 (plain), 8 elems/thread
__global__ void k_cvt(const float* __restrict__ s, __half* __restrict__ d, int n) {
    int stride = gridDim.x * blockDim.x;
    for (int i = blockIdx.x * blockDim.x + threadIdx.x; i < n / 8; i += stride) {
        float4 v0 = ((const float4*)s)[2 * i];
        float4 v1 = ((const float4*)s)[2 * i + 1];
        uint4 o;
        o.x = packh(__float2half_rn(v0.x), __float2half_rn(v0.y));
        o.y = packh(__float2half_rn(v0.z), __float2half_rn(v0.w));
        o.z = packh(__float2half_rn(v1.x), __float2half_rn(v1.y));
        o.w = packh(__float2half_rn(v1.z), __float2half_rn(v1.w));
        *(uint4*)(d + i * 8) = o;
    }
}

// routing (fp32 logits) + x fp16 conversion; one warp per token
__global__ void k_route(const float* __restrict__ x, const float* __restrict__ gw) {
    int t    = blockIdx.x * 8 + (threadIdx.x >> 5);
    int lane = threadIdx.x & 31;
    if (t >= TT) return;
    const float4* xr = (const float4*)(x + (size_t)t * DD);
    float acc[NE];
#pragma unroll
    for (int e = 0; e < NE; e++) acc[e] = 0.f;
    for (int i = lane; i < DD / 4; i += 32) {
        float4 xv = xr[i];
        *(uint2*)(&xs[t][i * 4]) = make_uint2(
            packh(__float2half_rn(xv.x), __float2half_rn(xv.y)),
            packh(__float2half_rn(xv.z), __float2half_rn(xv.w)));
#pragma unroll
        for (int e = 0; e < NE; e++) {
            float4 gv = ((const float4*)(gw + (size_t)e * DD))[i];
            acc[e] += xv.x * gv.x + xv.y * gv.y + xv.z * gv.z + xv.w * gv.w;
        }
    }
#pragma unroll
    for (int e = 0; e < NE; e++)
#pragma unroll
        for (int o = 16; o > 0; o >>= 1)
            acc[e] += __shfl_down_sync(0xffffffffu, acc[e], o);
    if (lane == 0) {
        float mx = acc[0];
#pragma unroll
        for (int e = 1; e < NE; e++) mx = fmaxf(mx, acc[e]);
        float p[NE];
#pragma unroll
        for (int e = 0; e < NE; e++) p[e] = expf(acc[e] - mx);
        int i1 = 0;
#pragma unroll
        for (int e = 1; e < NE; e++) if (p[e] > p[i1]) i1 = e;
        int i2 = (i1 == 0) ? 1 : 0;
#pragma unroll
        for (int e = 0; e < NE; e++) { if (e != i1 && p[e] > p[i2]) i2 = e; }
        float w1 = p[i1], w2 = p[i2];
        float inv = 1.0f / (w1 + w2);
        w1 *= inv; w2 *= inv;
        g_sel[t][0] = i1; g_sel[t][1] = i2;
        g_wgt[t][0] = w1; g_wgt[t][1] = w2;
        int b0 = i1 * 2;
        int s0 = atomicAdd(&g_cnt[b0], 1);
        g_tok[b0][s0] = t; g_twt[b0][s0] = w1;
        int b1 = i2 * 2 + 1;
        int s1 = atomicAdd(&g_cnt[b1], 1);
        g_tok[b1][s1] = t; g_twt[b1][s1] = w2;
    }
}

// ---------------- single-pass fp16 mma GEMM, cp.async double-buffered ----------------
enum { DOWN_S = 0, DOWN_R = 1, UP_S = 2, UP_R = 3 };

template <int MODE>
__global__ __launch_bounds__(256, 2) void k_mma(
    const float* __restrict__ bias, const float* __restrict__ bu,
    float* __restrict__ out, int kk)
{
    extern __shared__ char dyn[];
    __shared__ int   s_row[BM];
    __shared__ float s_wt[BM];

    const int tid = threadIdx.x, wid = tid >> 5, lane = tid & 31;
    const int m0 = blockIdx.x * BM, n0 = blockIdx.y * BN;

    int M = TT, eidx = 0, kidx = 0;
    const int* tok = nullptr;
    const float* twt = nullptr;
    if (MODE == DOWN_R || MODE == UP_R) {
        int bucket = (MODE == DOWN_R) ? (int)blockIdx.z : ((int)blockIdx.z * 2 + kk);
        M = g_cnt[bucket];
        if (m0 >= M) return;
        eidx = bucket >> 1;
        kidx = bucket & 1;
        tok = g_tok[bucket];
        twt = g_twt[bucket];
    }

    const __half* Ah; int lda;
    const __half* Bh; int ldb; int Kd;
    if (MODE == DOWN_S)      { Ah = &xs[0][0];        lda = DD; Bh = &wsdp[0][0];       ldb = DD; Kd = DD; }
    else if (MODE == DOWN_R) { Ah = &xs[0][0];        lda = DD; Bh = &wdp[eidx][0][0];  ldb = DD; Kd = DD; }
    else if (MODE == UP_S)   { Ah = &ghsp[0][0];      lda = BB; Bh = &wsup[0][0];       ldb = BB; Kd = BB; }
    else                     { Ah = &ghp[kk][0][0];   lda = BB; Bh = &wup[eidx][0][0];  ldb = BB; Kd = BB; }

    if (tid < BM) {
        int r = m0 + tid;
        if (MODE == DOWN_R || MODE == UP_R) {
            s_row[tid] = (r < M) ? tok[r] : -1;
            s_wt[tid]  = (r < M) ? twt[r] : 0.f;
        } else {
            s_row[tid] = r;
        }
    }
    __syncthreads();

    // cp.async: thread -> rows {lrow + 32*j}, 16B chunk lch (BK=64 -> 128B/row)
    const int lrow = tid >> 3, lch = tid & 7;
    const char* pA[4];
    uint32_t amask = 0;
#pragma unroll
    for (int j = 0; j < 4; j++) {
        int r = lrow + 32 * j;               // A row 0..127
        int sr = s_row[r];
        uint32_t ok = 1;
        if (MODE == DOWN_R || MODE == UP_R) {
            if (sr < 0) { sr = 0; ok = 0; }
        }
        amask |= ok << j;
        pA[j] = (const char*)(Ah + (size_t)sr * lda) + lch * 16;
    }
    const char* pB = (const char*)(Bh + (size_t)(n0 + lrow) * ldb) + lch * 16;
    const size_t bstride = (size_t)32 * ldb * 2;

    const uint32_t sb0 = smem_u32(dyn);
    const uint32_t sp0 = sb0 + (lrow * LDA + lch * 8) * 2;
    const uint32_t rowstep = 32 * LDA * 2;

    auto issue = [&](int stage) {
        uint32_t st = stage ? (uint32_t)STAGE_B : 0u;
#pragma unroll
        for (int j = 0; j < 4; j++)
            CPA16(sp0 + st + j * rowstep, pA[j], ((amask >> j) & 1) * 16);
#pragma unroll
        for (int j = 0; j < 4; j++)
            CPA16(sp0 + st + (j + 4) * rowstep, pB + j * bstride, 16);
        CPC();
#pragma unroll
        for (int j = 0; j < 4; j++) pA[j] += 128;
        pB += 128;
    };

    const int warp_m = wid >> 2, warp_n = wid & 3;   // 2 x 4 warps, 64x32 each
    float c[4][4][4];
#pragma unroll
    for (int i = 0; i < 4; i++)
#pragma unroll
        for (int j = 0; j < 4; j++)
#pragma unroll
            for (int q = 0; q < 4; q++) c[i][j][q] = 0.f;

    const int nch = Kd / BK;
    issue(0);

    for (int ch = 0; ch < nch; ch++) {
        if (ch + 1 < nch) { issue((ch + 1) & 1); CPW(1); }
        else              { CPW(0); }
        __syncthreads();

        const uint32_t sbase = sb0 + (ch & 1) * STAGE_B;
#pragma unroll
        for (int ks = 0; ks < 4; ks++) {
            uint32_t a[4][4], b[4][2];
            int arow = warp_m * 64 + (lane & 15);
            int acol = ks * 16 + (lane >> 4) * 8;
#pragma unroll
            for (int mt = 0; mt < 4; mt++)
                ldsm4(a[mt], sbase + ((arow + mt * 16) * LDA + acol) * 2);
            // B: rows 128+, ldsm4 loads two n-groups per issue
#pragma unroll
            for (int p = 0; p < 2; p++) {
                int brow = 128 + warp_n * 32 + p * 16 + ((lane >> 4) & 1) * 8 + (lane & 7);
                int bcol = ks * 16 + ((lane >> 3) & 1) * 8;
                uint32_t r4[4];
                ldsm4(r4, sbase + (brow * LDA + bcol) * 2);
                b[2 * p][0] = r4[0]; b[2 * p][1] = r4[1];
                b[2 * p + 1][0] = r4[2]; b[2 * p + 1][1] = r4[3];
            }
#pragma unroll
            for (int mt = 0; mt < 4; mt++)
#pragma unroll
                for (int nt = 0; nt < 4; nt++) mma16816(c[mt][nt], a[mt], b[nt]);
        }
        __syncthreads();
    }

    // ---------------- epilogue ----------------
    const int cbase = n0 + warp_n * 32 + (lane & 3) * 2;
#pragma unroll
    for (int mt = 0; mt < 4; mt++) {
#pragma unroll
        for (int half_i = 0; half_i < 2; half_i++) {
            int r = warp_m * 64 + mt * 16 + (lane >> 2) + half_i * 8;
            int t = s_row[r];
            if (t < 0) continue;
            float wgt = (MODE == DOWN_R) ? s_wt[r] : 0.f;
            int sel0 = 0, sel1 = 0; float w0 = 0.f, w1 = 0.f;
            if (MODE == UP_S) {
                sel0 = g_sel[t][0]; sel1 = g_sel[t][1];
                w0 = g_wgt[t][0];   w1 = g_wgt[t][1];
            }
#pragma unroll
            for (int nt = 0; nt < 4; nt++) {
                int n = cbase + nt * 8;
                float v0 = c[mt][nt][half_i * 2 + 0];
                float v1 = c[mt][nt][half_i * 2 + 1];
                if (MODE == DOWN_S) {
                    float o0 = gelu_f(v0 + bias[n]);
                    float o1 = gelu_f(v1 + bias[n + 1]);
                    *(uint32_t*)&ghsp[t][n] = packh(__float2half_rn(o0), __float2half_rn(o1));
                } else if (MODE == DOWN_R) {
                    const float* bp = bias + (size_t)eidx * BB + n;
                    float o0 = gelu_f(v0 + bp[0]) * wgt;
                    float o1 = gelu_f(v1 + bp[1]) * wgt;
                    *(uint32_t*)&ghp[kidx][t][n] = packh(__float2half_rn(o0), __float2half_rn(o1));
                } else if (MODE == UP_S) {
                    const float* b0p = bu + (size_t)sel0 * DD + n;
                    const float* b1p = bu + (size_t)sel1 * DD + n;
                    float2 o;
                    o.x = v0 + bias[n]     + w0 * b0p[0] + w1 * b1p[0];
                    o.y = v1 + bias[n + 1] + w0 * b0p[1] + w1 * b1p[1];
                    *(float2*)(out + (size_t)t * DD + n) = o;
                } else { // UP_R: race-free += (one slot per token per launch)
                    float* dp = out + (size_t)t * DD + n;
                    float2 old = *(float2*)dp;
                    old.x += v0; old.y += v1;
                    *(float2*)dp = old;
                }
            }
        }
    }
}

extern "C" void kernel_launch(void* const* d_in, const int* in_sizes, int n_in,
                              void* d_out, int out_size) {
    const float* x   = (const float*)d_in[0];
    const float* gw  = (const float*)d_in[1];
    const float* wd  = (const float*)d_in[2];
    const float* bd  = (const float*)d_in[3];
    const float* wu  = (const float*)d_in[4];
    const float* bu  = (const float*)d_in[5];
    const float* wsd = (const float*)d_in[6];
    const float* bsd = (const float*)d_in[7];
    const float* wsu = (const float*)d_in[8];
    const float* bsu = (const float*)d_in[9];
    float* out = (float*)d_out;

    cudaFuncSetAttribute(k_mma<DOWN_S>, cudaFuncAttributeMaxDynamicSharedMemorySize, DSMEM);
    cudaFuncSetAttribute(k_mma<DOWN_R>, cudaFuncAttributeMaxDynamicSharedMemorySize, DSMEM);
    cudaFuncSetAttribute(k_mma<UP_S>,   cudaFuncAttributeMaxDynamicSharedMemorySize, DSMEM);
    cudaFuncSetAttribute(k_mma<UP_R>,   cudaFuncAttributeMaxDynamicSharedMemorySize, DSMEM);

    __half *p_wd, *p_wu, *p_wsd, *p_wsu;
    cudaGetSymbolAddress((void**)&p_wd,  wdp);
    cudaGetSymbolAddress((void**)&p_wu,  wup);
    cudaGetSymbolAddress((void**)&p_wsd, wsdp);
    cudaGetSymbolAddress((void**)&p_wsu, wsup);

    k_reset<<<1, 32>>>();
    k_cvt<<<2048, 256>>>(wd,  p_wd,  NE * BB * DD);
    k_cvt<<<2048, 256>>>(wu,  p_wu,  NE * DD * BB);
    k_cvt<<<512, 256>>>(wsd, p_wsd, BB * DD);
    k_cvt<<<512, 256>>>(wsu, p_wsu, DD * BB);
    k_route<<<TT / 8, 256>>>(x, gw);

    k_mma<DOWN_S><<<dim3(TT / BM, BB / BN), 256, DSMEM>>>(bsd, nullptr, nullptr, 0);
    k_mma<DOWN_R><<<dim3(TT / BM, BB / BN, NBK), 256, DSMEM>>>(bd, nullptr, nullptr, 0);
    k_mma<UP_S><<<dim3(TT / BM, DD / BN), 256, DSMEM>>>(bsu, bu, out, 0);
    k_mma<UP_R><<<dim3(TT / BM, DD / BN, NE), 256, DSMEM>>>(nullptr, nullptr, out, 0);
    k_mma<UP_R><<<dim3(TT / BM, DD / BN, NE), 256, DSMEM>>>(nullptr, nullptr, out, 1);
}

// round 14
// speedup vs baseline: 1.0740x; 1.0736x over previous
#include <cuda_runtime.h>
#include <cuda_fp16.h>
#include <math.h>
#include <stdint.h>

#define TT   8192
#define DD   2048
#define NE   8
#define BB   512
#define NBK  16

#define BM   128
#define BN   128
#define BK   64
#define LDA  72                      // halves per smem row (128B data + 16B pad)
#define STAGE_B (256 * LDA * 2)      // 36864 B (128 A rows + 128 B rows)
#define DSMEM   (2 * STAGE_B)        // 73728 B

// ---------------- scratch (static device globals) ----------------
__device__ int    g_cnt[NBK];
__device__ int    g_tok[NBK][TT];
__device__ float  g_twt[NBK][TT];
__device__ int    g_sel[TT][2];
__device__ float  g_wgt[TT][2];
__device__ __align__(16) __half xs[TT][DD];
__device__ __align__(16) __half wdp[NE][BB][DD];
__device__ __align__(16) __half wup[NE][DD][BB];
__device__ __align__(16) __half wsdp[BB][DD];
__device__ __align__(16) __half wsup[DD][BB];
__device__ __align__(16) __half ghp[2][TT][BB];
__device__ __align__(16) __half ghsp[TT][BB];

__device__ __forceinline__ uint32_t smem_u32(const void* p) {
    uint32_t a;
    asm("{ .reg .u64 t; cvta.to.shared.u64 t, %1; cvt.u32.u64 %0, t; }" : "=r"(a) : "l"(p));
    return a;
}
__device__ __forceinline__ void ldsm4(uint32_t* r, uint32_t a) {
    asm volatile("ldmatrix.sync.aligned.m8n8.x4.shared.b16 {%0,%1,%2,%3}, [%4];"
                 : "=r"(r[0]), "=r"(r[1]), "=r"(r[2]), "=r"(r[3]) : "r"(a));
}
__device__ __forceinline__ void mma16816(float* c, const uint32_t* a, const uint32_t* b) {
    asm volatile("mma.sync.aligned.m16n8k16.row.col.f32.f16.f16.f32 "
                 "{%0,%1,%2,%3}, {%4,%5,%6,%7}, {%8,%9}, {%0,%1,%2,%3};"
                 : "+f"(c[0]), "+f"(c[1]), "+f"(c[2]), "+f"(c[3])
                 : "r"(a[0]), "r"(a[1]), "r"(a[2]), "r"(a[3]), "r"(b[0]), "r"(b[1]));
}
#define CPA16(dst, src, sz) \
    asm volatile("cp.async.cg.shared.global [%0], [%1], 16, %2;" \
                 :: "r"(dst), "l"(src), "r"(sz) : "memory")
#define CPC()  asm volatile("cp.async.commit_group;" ::: "memory")
#define CPW(n) asm volatile("cp.async.wait_group %0;" :: "n"(n) : "memory")

__device__ __forceinline__ uint32_t packh(half a, half b) {
    __half2 h = __halves2half2(a, b);
    return *(uint32_t*)&h;
}
__device__ __forceinline__ float gelu_f(float v) {
    return 0.5f * v * (1.0f + erff(v * 0.70710678118654752f));
}

// ---------------- setup kernels ----------------
__global__ void k_reset() {
    if (threadIdx.x < NBK) g_cnt[threadIdx.x] = 0;
}

#define N_WD  (NE * BB * DD)
#define N_WU  (NE * DD * BB)
#define N_WS  (BB * DD)

// single launch: convert all four weight tensors fp32 -> fp16
__global__ void k_cvt_all(const float* __restrict__ wd, const float* __restrict__ wu,
                          const float* __restrict__ wsd, const float* __restrict__ wsu) {
    const int total8 = (N_WD + N_WU + 2 * N_WS) / 8;
    int stride = gridDim.x * blockDim.x;
    for (int i = blockIdx.x * blockDim.x + threadIdx.x; i < total8; i += stride) {
        const float* s; __half* d; int off;
        if (i < N_WD / 8)                      { s = wd;  d = &wdp[0][0][0];  off = i; }
        else if (i < (N_WD + N_WU) / 8)        { s = wu;  d = &wup[0][0][0];  off = i - N_WD / 8; }
        else if (i < (N_WD + N_WU + N_WS) / 8) { s = wsd; d = &wsdp[0][0];    off = i - (N_WD + N_WU) / 8; }
        else                                   { s = wsu; d = &wsup[0][0];    off = i - (N_WD + N_WU + N_WS) / 8; }
        float4 v0 = ((const float4*)s)[2 * off];
        float4 v1 = ((const float4*)s)[2 * off + 1];
        uint4 o;
        o.x = packh(__float2half_rn(v0.x), __float2half_rn(v0.y));
        o.y = packh(__float2half_rn(v0.z), __float2half_rn(v0.w));
        o.z = packh(__float2half_rn(v1.x), __float2half_rn(v1.y));
        o.w = packh(__float2half_rn(v1.z), __float2half_rn(v1.w));
        *(uint4*)(d + (size_t)off * 8) = o;
    }
}

// routing (fp32 logits) + x fp16 conversion; one warp per token
__global__ void k_route(const float* __restrict__ x, const float* __restrict__ gw) {
    int t    = blockIdx.x * 8 + (threadIdx.x >> 5);
    int lane = threadIdx.x & 31;
    if (t >= TT) return;
    const float4* xr = (const float4*)(x + (size_t)t * DD);
    float acc[NE];
#pragma unroll
    for (int e = 0; e < NE; e++) acc[e] = 0.f;
    for (int i = lane; i < DD / 4; i += 32) {
        float4 xv = xr[i];
        *(uint2*)(&xs[t][i * 4]) = make_uint2(
            packh(__float2half_rn(xv.x), __float2half_rn(xv.y)),
            packh(__float2half_rn(xv.z), __float2half_rn(xv.w)));
#pragma unroll
        for (int e = 0; e < NE; e++) {
            float4 gv = ((const float4*)(gw + (size_t)e * DD))[i];
            acc[e] += xv.x * gv.x + xv.y * gv.y + xv.z * gv.z + xv.w * gv.w;
        }
    }
#pragma unroll
    for (int e = 0; e < NE; e++)
#pragma unroll
        for (int o = 16; o > 0; o >>= 1)
            acc[e] += __shfl_down_sync(0xffffffffu, acc[e], o);
    if (lane == 0) {
        float mx = acc[0];
#pragma unroll
        for (int e = 1; e < NE; e++) mx = fmaxf(mx, acc[e]);
        float p[NE];
#pragma unroll
        for (int e = 0; e < NE; e++) p[e] = expf(acc[e] - mx);
        int i1 = 0;
#pragma unroll
        for (int e = 1; e < NE; e++) if (p[e] > p[i1]) i1 = e;
        int i2 = (i1 == 0) ? 1 : 0;
#pragma unroll
        for (int e = 0; e < NE; e++) { if (e != i1 && p[e] > p[i2]) i2 = e; }
        float w1 = p[i1], w2 = p[i2];
        float inv = 1.0f / (w1 + w2);
        w1 *= inv; w2 *= inv;
        g_sel[t][0] = i1; g_sel[t][1] = i2;
        g_wgt[t][0] = w1; g_wgt[t][1] = w2;
        int b0 = i1 * 2;
        int s0 = atomicAdd(&g_cnt[b0], 1);
        g_tok[b0][s0] = t; g_twt[b0][s0] = w1;
        int b1 = i2 * 2 + 1;
        int s1 = atomicAdd(&g_cnt[b1], 1);
        g_tok[b1][s1] = t; g_twt[b1][s1] = w2;
    }
}

// ---------------- fp16 mma GEMM, cp.async double-buffered ----------------
// MDOWN: z=0..15 routed buckets -> ghp[k]; z=16 shared -> ghsp. K=2048.
// MUP0 : buckets (e,0), K=1024 concat [ghp0 | ghsp] x [wup[e] ; wsup]; writes out (+biases).
// MUP1 : buckets (e,1), K=512 ghp1 x wup[e]; out += acc.
enum { MDOWN = 0, MUP0 = 1, MUP1 = 2 };

template <int MODE>
__global__ __launch_bounds__(256, 2) void k_mma(
    const float* __restrict__ bias, const float* __restrict__ bias2,
    const float* __restrict__ bu, float* __restrict__ out)
{
    extern __shared__ char dyn[];
    __shared__ int   s_row[BM];
    __shared__ float s_wt[BM];

    const int tid = threadIdx.x, wid = tid >> 5, lane = tid & 31;
    const int m0 = blockIdx.x * BM, n0 = blockIdx.y * BN;

    int M = TT, eidx = 0, kidx = 0;
    bool shm = false;                 // MDOWN shared-expert slice
    const int* tok = nullptr;
    const float* twt = nullptr;
    if (MODE == MDOWN) {
        if (blockIdx.z == 16) {
            shm = true;
        } else {
            int bucket = blockIdx.z;
            M = g_cnt[bucket];
            if (m0 >= M) return;
            eidx = bucket >> 1;
            kidx = bucket & 1;
            tok = g_tok[bucket];
            twt = g_twt[bucket];
        }
    } else {
        int bucket = (MODE == MUP0) ? ((int)blockIdx.z * 2) : ((int)blockIdx.z * 2 + 1);
        M = g_cnt[bucket];
        if (m0 >= M) return;
        eidx = bucket >> 1;
        tok = g_tok[bucket];
        twt = g_twt[bucket];
    }

    // base pointers for A/B, split at chunk 'thr' (only MUP0 switches)
    const char *bA1, *bA2, *bB1, *bB2;
    int lda, Kd, thr;
    if (MODE == MDOWN) {
        lda = DD; Kd = DD; thr = 1 << 30;
        bA1 = bA2 = (const char*)&xs[0][0];
        bB1 = bB2 = shm ? (const char*)&wsdp[0][0] : (const char*)&wdp[eidx][0][0];
    } else if (MODE == MUP0) {
        lda = BB; Kd = 2 * BB; thr = 8;
        bA1 = (const char*)&ghp[0][0][0];   bA2 = (const char*)&ghsp[0][0];
        bB1 = (const char*)&wup[eidx][0][0]; bB2 = (const char*)&wsup[0][0];
    } else {
        lda = BB; Kd = BB; thr = 1 << 30;
        bA1 = bA2 = (const char*)&ghp[1][0][0];
        bB1 = bB2 = (const char*)&wup[eidx][0][0];
    }

    if (tid < BM) {
        int r = m0 + tid;
        if (MODE == MDOWN && shm) {
            s_row[tid] = r;
        } else {
            s_row[tid] = (r < M) ? tok[r] : -1;
            if (MODE == MDOWN) s_wt[tid] = (r < M) ? twt[r] : 0.f;
        }
    }
    __syncthreads();

    // cp.async: thread -> rows {lrow + 32*j}, 16B chunk lch (BK=64 -> 128B/row)
    const int lrow = tid >> 3, lch = tid & 7;
    size_t offA[4];
    uint32_t amask = 0;
#pragma unroll
    for (int j = 0; j < 4; j++) {
        int sr = s_row[lrow + 32 * j];
        uint32_t ok = 1;
        if (sr < 0) { sr = 0; ok = 0; }
        amask |= ok << j;
        offA[j] = (size_t)sr * lda * 2 + lch * 16;
    }
    const size_t offB = (size_t)(n0 + lrow) * lda * 2 + lch * 16;
    const size_t bstride = (size_t)32 * lda * 2;

    const uint32_t sb0 = smem_u32(dyn);
    const uint32_t sp0 = sb0 + (lrow * LDA + lch * 8) * 2;
    const uint32_t rowstep = 32 * LDA * 2;

    auto issue = [&](int ch, int stage) {
        const char* bA; const char* bB; int cc;
        if (ch < thr) { bA = bA1; bB = bB1; cc = ch; }
        else          { bA = bA2; bB = bB2; cc = ch - thr; }
        uint32_t st = stage ? (uint32_t)STAGE_B : 0u;
        size_t cb = (size_t)cc * 128;
#pragma unroll
        for (int j = 0; j < 4; j++)
            CPA16(sp0 + st + j * rowstep, bA + offA[j] + cb, ((amask >> j) & 1) * 16);
#pragma unroll
        for (int j = 0; j < 4; j++)
            CPA16(sp0 + st + (j + 4) * rowstep, bB + offB + j * bstride + cb, 16u);
        CPC();
    };

    const int warp_m = wid >> 2, warp_n = wid & 3;   // 2 x 4 warps, 64x32 each
    float c[4][4][4];
#pragma unroll
    for (int i = 0; i < 4; i++)
#pragma unroll
        for (int j = 0; j < 4; j++)
#pragma unroll
            for (int q = 0; q < 4; q++) c[i][j][q] = 0.f;

    const int nch = Kd / BK;
    issue(0, 0);

    for (int ch = 0; ch < nch; ch++) {
        if (ch + 1 < nch) { issue(ch + 1, (ch + 1) & 1); CPW(1); }
        else              { CPW(0); }
        __syncthreads();

        const uint32_t sbase = sb0 + (ch & 1) * STAGE_B;
#pragma unroll
        for (int ks = 0; ks < 4; ks++) {
            uint32_t a[4][4], b[4][2];
            int arow = warp_m * 64 + (lane & 15);
            int acol = ks * 16 + (lane >> 4) * 8;
#pragma unroll
            for (int mt = 0; mt < 4; mt++)
                ldsm4(a[mt], sbase + ((arow + mt * 16) * LDA + acol) * 2);
#pragma unroll
            for (int p = 0; p < 2; p++) {
                int brow = 128 + warp_n * 32 + p * 16 + ((lane >> 4) & 1) * 8 + (lane & 7);
                int bcol = ks * 16 + ((lane >> 3) & 1) * 8;
                uint32_t r4[4];
                ldsm4(r4, sbase + (brow * LDA + bcol) * 2);
                b[2 * p][0] = r4[0]; b[2 * p][1] = r4[1];
                b[2 * p + 1][0] = r4[2]; b[2 * p + 1][1] = r4[3];
            }
#pragma unroll
            for (int mt = 0; mt < 4; mt++)
#pragma unroll
                for (int nt = 0; nt < 4; nt++) mma16816(c[mt][nt], a[mt], b[nt]);
        }
        __syncthreads();
    }

    // ---------------- epilogue ----------------
    const int cbase = n0 + warp_n * 32 + (lane & 3) * 2;
#pragma unroll
    for (int mt = 0; mt < 4; mt++) {
#pragma unroll
        for (int half_i = 0; half_i < 2; half_i++) {
            int r = warp_m * 64 + mt * 16 + (lane >> 2) + half_i * 8;
            int t = s_row[r];
            if (t < 0) continue;
            float wgt = (MODE == MDOWN && !shm) ? s_wt[r] : 0.f;
            int sel0 = 0, sel1 = 0; float w0 = 0.f, w1 = 0.f;
            if (MODE == MUP0) {
                sel0 = g_sel[t][0]; sel1 = g_sel[t][1];
                w0 = g_wgt[t][0];   w1 = g_wgt[t][1];
            }
#pragma unroll
            for (int nt = 0; nt < 4; nt++) {
                int n = cbase + nt * 8;
                float v0 = c[mt][nt][half_i * 2 + 0];
                float v1 = c[mt][nt][half_i * 2 + 1];
                if (MODE == MDOWN) {
                    if (shm) {
                        float o0 = gelu_f(v0 + bias2[n]);
                        float o1 = gelu_f(v1 + bias2[n + 1]);
                        *(uint32_t*)&ghsp[t][n] = packh(__float2half_rn(o0), __float2half_rn(o1));
                    } else {
                        const float* bp = bias + (size_t)eidx * BB + n;
                        float o0 = gelu_f(v0 + bp[0]) * wgt;
                        float o1 = gelu_f(v1 + bp[1]) * wgt;
                        *(uint32_t*)&ghp[kidx][t][n] = packh(__float2half_rn(o0), __float2half_rn(o1));
                    }
                } else if (MODE == MUP0) {
                    // fused routed-k0 + shared up-projection; sole writer of out
                    const float* b0p = bu + (size_t)sel0 * DD + n;
                    const float* b1p = bu + (size_t)sel1 * DD + n;
                    float2 o;
                    o.x = v0 + bias[n]     + w0 * b0p[0] + w1 * b1p[0];
                    o.y = v1 + bias[n + 1] + w0 * b0p[1] + w1 * b1p[1];
                    *(float2*)(out + (size_t)t * DD + n) = o;
                } else { // MUP1: race-free += (one slot per token)
                    float* dp = out + (size_t)t * DD + n;
                    float2 old = *(float2*)dp;
                    old.x += v0; old.y += v1;
                    *(float2*)dp = old;
                }
            }
        }
    }
}

extern "C" void kernel_launch(void* const* d_in, const int* in_sizes, int n_in,
                              void* d_out, int out_size) {
    const float* x   = (const float*)d_in[0];
    const float* gw  = (const float*)d_in[1];
    const float* wd  = (const float*)d_in[2];
    const float* bd  = (const float*)d_in[3];
    const float* wu  = (const float*)d_in[4];
    const float* bu  = (const float*)d_in[5];
    const float* wsd = (const float*)d_in[6];
    const float* bsd = (const float*)d_in[7];
    const float* wsu = (const float*)d_in[8];
    const float* bsu = (const float*)d_in[9];
    float* out = (float*)d_out;

    cudaFuncSetAttribute(k_mma<MDOWN>, cudaFuncAttributeMaxDynamicSharedMemorySize, DSMEM);
    cudaFuncSetAttribute(k_mma<MUP0>,  cudaFuncAttributeMaxDynamicSharedMemorySize, DSMEM);
    cudaFuncSetAttribute(k_mma<MUP1>,  cudaFuncAttributeMaxDynamicSharedMemorySize, DSMEM);

    k_reset<<<1, 32>>>();
    k_cvt_all<<<4096, 256>>>(wd, wu, wsd, wsu);
    k_route<<<TT / 8, 256>>>(x, gw);

    // down: routed buckets (z=0..15) + shared (z=16), K=2048, N=512
    k_mma<MDOWN><<<dim3(TT / BM, BB / BN, 17), 256, DSMEM>>>(bd, bsd, nullptr, out);
    // up k0 fused with shared (K=1024): writes every out element exactly once
    k_mma<MUP0><<<dim3(TT / BM, DD / BN, NE), 256, DSMEM>>>(bsu, nullptr, bu, out);
    // up k1: race-free +=
    k_mma<MUP1><<<dim3(TT / BM, DD / BN, NE), 256, DSMEM>>>(nullptr, nullptr, nullptr, out);
}